// round 1
// baseline (speedup 1.0000x reference)
#include <cuda_runtime.h>

// EnhancedLIFNeuron: Conv1d(1,1,5,'same') over T + spatial attention + LIF scan.
// B=128, T=128, F=2048. One thread owns one (b,f) chain.
// Single kernel: stage x[b, :, f0:f0+128] tile into SMEM (float4 coalesced),
// compute per-chain mean of conv output in closed form (boundary-corrected),
// then run conv + LIF from SMEM with a rolling 5-tap window.

#define Tn 128
#define Fn 2048
#define Bn 128
#define CH 128   // chains per block == blockDim.x

__global__ __launch_bounds__(CH, 3)
void lif_kernel(const float* __restrict__ x,
                const float* __restrict__ thr0p,
                const float* __restrict__ convw,
                const float* __restrict__ convb,
                const float* __restrict__ sap,
                float* __restrict__ out)
{
    extern __shared__ float sm[];  // [Tn][CH] = 64 KB
    const int tid = threadIdx.x;
    const int b   = blockIdx.x >> 4;          // Fn/CH = 16 blocks per batch
    const int f0  = (blockIdx.x & 15) << 7;   // * CH

    // ---- stage tile: x[b, t, f0 + 0..127] for all t, float4 coalesced ----
    const float4* __restrict__ src =
        reinterpret_cast<const float4*>(x + (size_t)b * Tn * Fn + f0);
    float4* s4 = reinterpret_cast<float4*>(sm);
    #pragma unroll 8
    for (int i = tid; i < Tn * (CH / 4); i += CH) {
        int t = i >> 5;        // CH/4 = 32 float4 per row
        int c = i & 31;
        s4[t * 32 + c] = src[(size_t)t * (Fn / 4) + c];
    }
    __syncthreads();

    // ---- scalars (broadcast loads, L1-cached) ----
    const float thr0 = thr0p[0];
    const float w0 = convw[0], w1 = convw[1], w2 = convw[2], w3 = convw[3], w4 = convw[4];
    const float cb = convb[0];
    const float sa = sap[0];

    // ---- pass A: per-chain sum over t  ->  mean of conv output (closed form) ----
    float a0 = 0.f, a1 = 0.f, a2 = 0.f, a3 = 0.f;
    #pragma unroll 8
    for (int t = 0; t < Tn; t += 4) {
        a0 += sm[(t + 0) * CH + tid];
        a1 += sm[(t + 1) * CH + tid];
        a2 += sm[(t + 2) * CH + tid];
        a3 += sm[(t + 3) * CH + tid];
    }
    const float S = (a0 + a1) + (a2 + a3);
    const float xb0   = sm[0 * CH + tid];
    const float xb1   = sm[1 * CH + tid];
    const float xb126 = sm[126 * CH + tid];
    const float xb127 = sm[127 * CH + tid];
    // sum_t conv_raw[t] = W*S - (w3+w4)x0 - w4*x1 - w0*x126 - (w0+w1)*x127
    const float W = ((w0 + w1) + w2) + (w3 + w4);
    float mean = (W * S - (w3 + w4) * xb0 - w4 * xb1
                        - w0 * xb126 - (w0 + w1) * xb127) * (1.0f / Tn) + cb;
    const float attw  = 1.0f / (1.0f + __expf(-sa * mean));
    const float scale = 1.0f + 0.5f * attw;           // GAMMA = 0.5

    // ---- pass B: conv (rolling window) + LIF scan ----
    const float PI     = 3.14159265358979323846f;
    const float C_ARG  = PI * 0.5f;                   // pi/2
    const float C_SPK  = 0.5f / PI;                   // 1/(2*pi)
    const float C_THR0 = 0.1f * thr0;                 // (1-ALPHA)*init_threshold
    const float C_AVG  = 0.1f / 3.0f;                 // BETA / 3

    float mem = 0.f, thr = thr0, h1 = 0.f, h2 = 0.f;
    float xm2 = 0.f, xm1 = 0.f;
    float xc  = sm[0 * CH + tid];
    float xp1 = sm[1 * CH + tid];
    float xp2 = sm[2 * CH + tid];

    float* __restrict__ op = out + (size_t)b * Tn * Fn + f0 + tid;

    #pragma unroll 4
    for (int t = 0; t < Tn; t++) {
        // conv_raw[t] + bias  (cross-correlation, 'SAME' padding)
        float conv = fmaf(w0, xm2,
                     fmaf(w1, xm1,
                     fmaf(w2, xc,
                     fmaf(w3, xp1,
                     fmaf(w4, xp2, cb)))));
        float xs = conv * scale;
        mem = fmaf(0.9f, mem, xs);                            // DECAY
        float spike = fmaf(atanf((mem - thr) * C_ARG), C_SPK, 0.25f);
        float avg3 = (h1 + h2) + spike;
        thr = fmaf(0.9f, thr, fmaf(C_AVG, avg3, C_THR0));     // ALPHA, BETA
        mem = fmaf(-spike, thr, mem);
        op[(size_t)t * Fn] = spike;
        h1 = h2; h2 = spike;
        xm2 = xm1; xm1 = xc; xc = xp1; xp1 = xp2;
        xp2 = (t + 3 < Tn) ? sm[(t + 3) * CH + tid] : 0.f;
    }

    // final membrane potential: out[B*T*F + b*F + f]
    out[(size_t)Bn * Tn * Fn + (size_t)b * Fn + f0 + tid] = mem;
}

extern "C" void kernel_launch(void* const* d_in, const int* in_sizes, int n_in,
                              void* d_out, int out_size)
{
    (void)in_sizes; (void)n_in; (void)out_size;
    const float* x    = (const float*)d_in[0];
    const float* thr0 = (const float*)d_in[1];
    const float* cw   = (const float*)d_in[2];
    const float* cbp  = (const float*)d_in[3];
    const float* sa   = (const float*)d_in[4];
    float* out = (float*)d_out;

    cudaFuncSetAttribute(lif_kernel, cudaFuncAttributeMaxDynamicSharedMemorySize,
                         Tn * CH * (int)sizeof(float));
    lif_kernel<<<Bn * (Fn / CH), CH, Tn * CH * sizeof(float)>>>(x, thr0, cw, cbp, sa, out);
}